// round 7
// baseline (speedup 1.0000x reference)
#include <cuda_runtime.h>

#define NEG_INF (-1e30f)
#define BB 32
#define NN 256
#define KNB 20

// Scratch (device globals; no allocations allowed)
__device__ int   g_idx[BB*NN*KNB];
__device__ float g_H  [BB*NN*256];
__device__ float g_H2 [BB*NN*128];
__device__ float g_w2T[64*128];
__device__ float g_w3T[128*256];
__device__ float g_w1T[256*128];

// ---------------------------------------------------------------------------
// Kernel 0: one-time weight transposes
// ---------------------------------------------------------------------------
__global__ __launch_bounds__(256) void transpose_kernel(
    const float* __restrict__ w2, const float* __restrict__ w3,
    const float* __restrict__ fc1w)
{
    int tid = blockIdx.x*256 + threadIdx.x;
    if (tid < 8192) { int c = tid >> 7, o = tid & 127; g_w2T[tid] = w2[o*64 + c]; }
    int t2 = tid - 8192;
    if (t2 >= 0 && t2 < 32768) { int c = t2 >> 8, o = t2 & 255; g_w3T[t2] = w3[o*128 + c]; }
    int t3 = tid - 40960;
    if (t3 >= 0 && t3 < 32768) { int n = t3 >> 7, o = t3 & 127; g_w1T[t3] = fc1w[o*256 + n]; }
}

// ---------------------------------------------------------------------------
// Kernel 1: kNN (one row/warp, redux argmax)
// ---------------------------------------------------------------------------
__global__ __launch_bounds__(256) void knn_kernel(const float* __restrict__ x) {
    __shared__ float xs0[NN], xs1[NN], xs2[NN], xxs[NN];
    int b      = blockIdx.x >> 5;
    int n_base = (blockIdx.x & 31) * 8;
    int tid = threadIdx.x;
    {
        float a0 = x[(b*NN + tid)*3 + 0];
        float a1 = x[(b*NN + tid)*3 + 1];
        float a2 = x[(b*NN + tid)*3 + 2];
        xs0[tid] = a0; xs1[tid] = a1; xs2[tid] = a2;
        xxs[tid] = a0*a0 + a1*a1 + a2*a2;
    }
    __syncthreads();
    int w = tid >> 5, lane = tid & 31;
    int i = n_base + w;

    float xi0 = xs0[i], xi1 = xs1[i], xi2 = xs2[i], xxi = xxs[i];
    unsigned m[8];
    #pragma unroll
    for (int t = 0; t < 8; t++) {
        int j = lane + 32*t;
        float dv = 2.f*(xi0*xs0[j] + xi1*xs1[j] + xi2*xs2[j]) - xxi - xxs[j];
        unsigned u = __float_as_uint(dv);
        m[t] = u ^ (unsigned)(((int)u >> 31) | 0x80000000);
    }

    int myj = 0;
    #pragma unroll 4
    for (int kk = 0; kk < KNB; kk++) {
        unsigned bv = m[0]; int bj = lane;
        #pragma unroll
        for (int t = 1; t < 8; t++)
            if (m[t] > bv) { bv = m[t]; bj = lane + 32*t; }
        unsigned vmax = __reduce_max_sync(0xffffffffu, bv);
        unsigned cand = (bv == vmax) ? (unsigned)bj : 0x7fffffffu;
        int jwin = (int)__reduce_min_sync(0xffffffffu, cand);
        if (lane == kk) myj = jwin;
        if ((jwin & 31) == lane) {
            int t = jwin >> 5;
            #pragma unroll
            for (int tt = 0; tt < 8; tt++) if (tt == t) m[tt] = 0u;
        }
    }
    if (lane < KNB) g_idx[(b*NN + i)*KNB + lane] = myj;
}

// ---------------------------------------------------------------------------
// Kernel 2a: mlp12  3 -> 64 -> 128
// ---------------------------------------------------------------------------
#define MLP12_SMEM ((96 + 2048 + 8192)*4)
__global__ __launch_bounds__(256) void mlp12_kernel(
    const float* __restrict__ x,
    const float* __restrict__ w1, const float* __restrict__ s1, const float* __restrict__ t1,
    const float* __restrict__ s2, const float* __restrict__ t2)
{
    extern __shared__ float sm[];
    float* xs   = sm;
    float* H1s  = sm + 96;
    float* W2Ts = sm + 2144;

    int tid = threadIdx.x;
    int row_base = blockIdx.x * 32;
    int b = row_base >> 8;
    int j0 = row_base & 255;

    if (tid < 96) xs[tid] = x[b*768 + j0*3 + tid];
    for (int e = tid; e < 2048; e += 256)
        ((float4*)W2Ts)[e] = ((const float4*)g_w2T)[e];
    __syncthreads();

    int w = tid >> 5, lane = tid & 31;
    int rb = w * 4;

    {
        int o2 = lane + 32;
        float a0 = w1[lane*3], a1 = w1[lane*3+1], a2 = w1[lane*3+2];
        float b0 = w1[o2*3],   b1 = w1[o2*3+1],   b2 = w1[o2*3+2];
        float sa = s1[lane], ta = t1[lane], sb = s1[o2], tb = t1[o2];
        #pragma unroll
        for (int i = 0; i < 4; i++) {
            int row = rb + i;
            float x0 = xs[row*3], x1 = xs[row*3+1], x2 = xs[row*3+2];
            H1s[row*64 + lane]      = fmaxf(sa*(a0*x0 + a1*x1 + a2*x2) + ta, 0.f);
            H1s[row*64 + lane + 32] = fmaxf(sb*(b0*x0 + b1*x1 + b2*x2) + tb, 0.f);
        }
    }
    __syncthreads();

    float acc[4][4];
    #pragma unroll
    for (int i = 0; i < 4; i++)
        #pragma unroll
        for (int k = 0; k < 4; k++) acc[i][k] = 0.f;
    #pragma unroll 8
    for (int c = 0; c < 64; c++) {
        float4 wv = *(const float4*)&W2Ts[c*128 + lane*4];
        #pragma unroll
        for (int i = 0; i < 4; i++) {
            float h = H1s[(rb+i)*64 + c];
            acc[i][0] += h*wv.x; acc[i][1] += h*wv.y;
            acc[i][2] += h*wv.z; acc[i][3] += h*wv.w;
        }
    }
    float sv[4], tv[4];
    #pragma unroll
    for (int k = 0; k < 4; k++) { sv[k] = s2[lane*4+k]; tv[k] = t2[lane*4+k]; }
    #pragma unroll
    for (int i = 0; i < 4; i++) {
        float4 o;
        o.x = fmaxf(sv[0]*acc[i][0] + tv[0], 0.f);
        o.y = fmaxf(sv[1]*acc[i][1] + tv[1], 0.f);
        o.z = fmaxf(sv[2]*acc[i][2] + tv[2], 0.f);
        o.w = fmaxf(sv[3]*acc[i][3] + tv[3], 0.f);
        *(float4*)&g_H2[(row_base + rb + i)*128 + lane*4] = o;
    }
}

// ---------------------------------------------------------------------------
// Kernel 2b: mlp3  128 -> 256, software-pipelined h prefetch.
// ---------------------------------------------------------------------------
#define MLP3_SMEM ((8192 + 16384)*4)
__global__ __launch_bounds__(256, 2) void mlp3_kernel(
    const float* __restrict__ s3, const float* __restrict__ t3)
{
    extern __shared__ float sm[];
    float* H2s  = sm;          // [64 rows][128 c]
    float* W3Ts = sm + 8192;   // [128 c][128 o_local]

    int bid = blockIdx.x;
    int row0 = (bid >> 1) * 64;
    int oh = bid & 1;
    int tid = threadIdx.x;

    for (int e = tid; e < 2048; e += 256)
        ((float4*)H2s)[e] = ((const float4*)(g_H2 + row0*128))[e];
    for (int e = tid; e < 4096; e += 256) {
        int c = e >> 5, q = e & 31;
        ((float4*)W3Ts)[e] = *(const float4*)(g_w3T + c*256 + oh*128 + q*4);
    }
    __syncthreads();

    int w = tid >> 5, lane = tid & 31;
    int rb = w*8 + (lane >> 4)*4;
    int ob = (lane & 15)*8;

    float acc[4][8];
    #pragma unroll
    for (int i = 0; i < 4; i++)
        #pragma unroll
        for (int k = 0; k < 8; k++) acc[i][k] = 0.f;

    float4 h_cur[4], h_nxt[4];
    #pragma unroll
    for (int i = 0; i < 4; i++)
        h_cur[i] = *(const float4*)&H2s[(rb+i)*128];

    #pragma unroll 2
    for (int c = 0; c < 128; c += 4) {
        if (c + 4 < 128) {
            #pragma unroll
            for (int i = 0; i < 4; i++)
                h_nxt[i] = *(const float4*)&H2s[(rb+i)*128 + c + 4];
        }
        #pragma unroll
        for (int cc = 0; cc < 4; cc++) {
            float4 wa = *(const float4*)&W3Ts[(c+cc)*128 + ob];
            float4 wb = *(const float4*)&W3Ts[(c+cc)*128 + ob + 4];
            #pragma unroll
            for (int i = 0; i < 4; i++) {
                float hv = ((const float*)&h_cur[i])[cc];
                acc[i][0] += hv*wa.x; acc[i][1] += hv*wa.y;
                acc[i][2] += hv*wa.z; acc[i][3] += hv*wa.w;
                acc[i][4] += hv*wb.x; acc[i][5] += hv*wb.y;
                acc[i][6] += hv*wb.z; acc[i][7] += hv*wb.w;
            }
        }
        #pragma unroll
        for (int i = 0; i < 4; i++) h_cur[i] = h_nxt[i];
    }
    float sv[8], tv[8];
    #pragma unroll
    for (int k = 0; k < 8; k++) { sv[k] = s3[oh*128 + ob + k]; tv[k] = t3[oh*128 + ob + k]; }
    #pragma unroll
    for (int i = 0; i < 4; i++) {
        int row = row0 + rb + i;
        float4 oa, obv;
        oa.x  = fmaxf(sv[0]*acc[i][0] + tv[0], 0.f);
        oa.y  = fmaxf(sv[1]*acc[i][1] + tv[1], 0.f);
        oa.z  = fmaxf(sv[2]*acc[i][2] + tv[2], 0.f);
        oa.w  = fmaxf(sv[3]*acc[i][3] + tv[3], 0.f);
        obv.x = fmaxf(sv[4]*acc[i][4] + tv[4], 0.f);
        obv.y = fmaxf(sv[5]*acc[i][5] + tv[5], 0.f);
        obv.z = fmaxf(sv[6]*acc[i][6] + tv[6], 0.f);
        obv.w = fmaxf(sv[7]*acc[i][7] + tv[7], 0.f);
        *(float4*)&g_H[row*256 + oh*128 + ob]     = oa;
        *(float4*)&g_H[row*256 + oh*128 + ob + 4] = obv;
    }
}

// ---------------------------------------------------------------------------
// Kernel 3: FUSED gather-max + fc1 + fc2, fc1 loop software-pipelined.
// ---------------------------------------------------------------------------
#define MAXFC_SMEM ((16384 + 32768 + 5120)*4)
__global__ __launch_bounds__(512) void maxfc_kernel(
    const float* __restrict__ fc1_b,
    const float* __restrict__ fc2_w, const float* __restrict__ fc2_b,
    float* __restrict__ out)
{
    extern __shared__ float sm[];
    float* Ms   = sm;           // [n 256][c 64]
    float* Hs   = sm + 16384;   // [j 256][c 64]  (phase A)
    float* W1Ts = sm + 16384;   // [n 256][o 128] (phase B overlay)
    float* W2s  = sm + 49152;   // [q 40][o 128]
    int b = blockIdx.x >> 2, ct = blockIdx.x & 3;
    int tid = threadIdx.x;
    int w = tid >> 5, lane = tid & 31;

    // ---- Phase A: stage H channel-slice, gather-max into Ms
    for (int e = tid; e < 4096; e += 512) {
        int j = e >> 4, q = e & 15;
        ((float4*)Hs)[e] = *(const float4*)(g_H + (b*256 + j)*256 + ct*64 + q*4);
    }
    __syncthreads();

    #pragma unroll 2
    for (int t = 0; t < 16; t += 2) {
        int n0 = w*16 + t, n1 = n0 + 1;
        const int4* ip0 = (const int4*)(g_idx + (b*NN + n0)*KNB);
        const int4* ip1 = (const int4*)(g_idx + (b*NN + n1)*KNB);
        float a0 = NEG_INF, a1 = NEG_INF, c0 = NEG_INF, c1 = NEG_INF;
        #pragma unroll
        for (int q = 0; q < 5; q++) {
            int4 u = ip0[q];
            int4 v = ip1[q];
            a0 = fmaxf(a0, Hs[u.x*64 + lane]); a1 = fmaxf(a1, Hs[u.x*64 + lane + 32]);
            c0 = fmaxf(c0, Hs[v.x*64 + lane]); c1 = fmaxf(c1, Hs[v.x*64 + lane + 32]);
            a0 = fmaxf(a0, Hs[u.y*64 + lane]); a1 = fmaxf(a1, Hs[u.y*64 + lane + 32]);
            c0 = fmaxf(c0, Hs[v.y*64 + lane]); c1 = fmaxf(c1, Hs[v.y*64 + lane + 32]);
            a0 = fmaxf(a0, Hs[u.z*64 + lane]); a1 = fmaxf(a1, Hs[u.z*64 + lane + 32]);
            c0 = fmaxf(c0, Hs[v.z*64 + lane]); c1 = fmaxf(c1, Hs[v.z*64 + lane + 32]);
            a0 = fmaxf(a0, Hs[u.w*64 + lane]); a1 = fmaxf(a1, Hs[u.w*64 + lane + 32]);
            c0 = fmaxf(c0, Hs[v.w*64 + lane]); c1 = fmaxf(c1, Hs[v.w*64 + lane + 32]);
        }
        Ms[n0*64 + lane] = a0; Ms[n0*64 + lane + 32] = a1;
        Ms[n1*64 + lane] = c0; Ms[n1*64 + lane + 32] = c1;
    }
    __syncthreads();

    // ---- Phase B: load weights over dead Hs region, then fc1 + fc2
    for (int e = tid; e < 8192; e += 512)
        ((float4*)W1Ts)[e] = ((const float4*)g_w1T)[e];
    for (int e = tid; e < 1280; e += 512)
        ((float4*)W2s)[e] = ((const float4*)fc2_w)[e];
    __syncthreads();

    int half = w >> 3, w8 = w & 7;
    int o_base = w8*16 + (lane >> 4)*8;
    int c_base = (lane & 15)*4;

    float acc[4][8];
    #pragma unroll
    for (int i = 0; i < 4; i++)
        #pragma unroll
        for (int k = 0; k < 8; k++) acc[i][k] = 0.f;

    int n0 = half*128;
    float4 mv_c = *(const float4*)&Ms[n0*64 + c_base];
    float4 wa_c = *(const float4*)&W1Ts[n0*128 + o_base];
    float4 wb_c = *(const float4*)&W1Ts[n0*128 + o_base + 4];
    #pragma unroll 4
    for (int n = n0; n < n0 + 128; n++) {
        float4 mv = mv_c, wa = wa_c, wb = wb_c;
        if (n + 1 < n0 + 128) {
            mv_c = *(const float4*)&Ms[(n+1)*64 + c_base];
            wa_c = *(const float4*)&W1Ts[(n+1)*128 + o_base];
            wb_c = *(const float4*)&W1Ts[(n+1)*128 + o_base + 4];
        }
        float mm[4] = {mv.x, mv.y, mv.z, mv.w};
        float ww[8] = {wa.x, wa.y, wa.z, wa.w, wb.x, wb.y, wb.z, wb.w};
        #pragma unroll
        for (int i = 0; i < 4; i++)
            #pragma unroll
            for (int k = 0; k < 8; k++)
                acc[i][k] += mm[i]*ww[k];
    }
    __syncthreads();

    float* Rs = sm;
    float* Gs = sm + 8320;
    if (half == 1) {
        #pragma unroll
        for (int i = 0; i < 4; i++)
            #pragma unroll
            for (int k = 0; k < 8; k++)
                Rs[(c_base + i)*129 + o_base + k] = acc[i][k];
    }
    __syncthreads();
    if (half == 0) {
        float b1v[8];
        #pragma unroll
        for (int k = 0; k < 8; k++) b1v[k] = fc1_b[o_base + k];
        #pragma unroll
        for (int i = 0; i < 4; i++)
            #pragma unroll
            for (int k = 0; k < 8; k++)
                Gs[(c_base + i)*129 + o_base + k] =
                    fmaxf(acc[i][k] + Rs[(c_base + i)*129 + o_base + k] + b1v[k], 0.f);
    }
    __syncthreads();

    if (w < 8) {
        float acc2[2][5];
        #pragma unroll
        for (int h = 0; h < 2; h++)
            #pragma unroll
            for (int q = 0; q < 5; q++) acc2[h][q] = 0.f;
        #pragma unroll 4
        for (int o = 0; o < 128; o++) {
            float ga = Gs[lane*129 + o];
            float gb = Gs[(lane + 32)*129 + o];
            #pragma unroll
            for (int q = 0; q < 5; q++) {
                float wv = W2s[(w*5 + q)*128 + o];
                acc2[0][q] += ga*wv;
                acc2[1][q] += gb*wv;
            }
        }
        #pragma unroll
        for (int h = 0; h < 2; h++) {
            int cg = ct*64 + lane + h*32;
            #pragma unroll
            for (int q = 0; q < 5; q++)
                out[(b*256 + cg)*40 + w*5 + q] = acc2[h][q] + fc2_b[w*5 + q];
        }
    }
}

extern "C" void kernel_launch(void* const* d_in, const int* in_sizes, int n_in,
                              void* d_out, int out_size) {
    const float* x    = (const float*)d_in[0];
    const float* w1   = (const float*)d_in[1];
    const float* s1   = (const float*)d_in[2];
    const float* t1   = (const float*)d_in[3];
    const float* w2   = (const float*)d_in[4];
    const float* s2   = (const float*)d_in[5];
    const float* t2   = (const float*)d_in[6];
    const float* w3   = (const float*)d_in[7];
    const float* s3   = (const float*)d_in[8];
    const float* t3   = (const float*)d_in[9];
    const float* fc1w = (const float*)d_in[10];
    const float* fc1b = (const float*)d_in[11];
    const float* fc2w = (const float*)d_in[12];
    const float* fc2b = (const float*)d_in[13];
    float* out = (float*)d_out;

    cudaFuncSetAttribute(mlp12_kernel, cudaFuncAttributeMaxDynamicSharedMemorySize, MLP12_SMEM);
    cudaFuncSetAttribute(mlp3_kernel,  cudaFuncAttributeMaxDynamicSharedMemorySize, MLP3_SMEM);
    cudaFuncSetAttribute(maxfc_kernel, cudaFuncAttributeMaxDynamicSharedMemorySize, MAXFC_SMEM);

    transpose_kernel<<<288, 256>>>(w2, w3, fc1w);
    knn_kernel<<<1024, 256>>>(x);
    mlp12_kernel<<<256, 256, MLP12_SMEM>>>(x, w1, s1, t1, s2, t2);
    mlp3_kernel<<<256, 256, MLP3_SMEM>>>(s3, t3);
    maxfc_kernel<<<128, 512, MAXFC_SMEM>>>(fc1b, fc2w, fc2b, out);
}

// round 8
// speedup vs baseline: 1.1278x; 1.1278x over previous
#include <cuda_runtime.h>

#define NEG_INF (-1e30f)
#define BB 32
#define NN 256
#define KNB 20

// Scratch (device globals; no allocations allowed)
__device__ int   g_idx[BB*NN*KNB];
__device__ float g_H  [BB*NN*256];
__device__ float g_H2 [BB*NN*128];
__device__ float g_w2T[64*128];
__device__ float g_w3T[128*256];
__device__ float g_w1T[256*128];

// ---------------------------------------------------------------------------
// Kernel 0: one-time weight transposes
// ---------------------------------------------------------------------------
__global__ __launch_bounds__(256) void transpose_kernel(
    const float* __restrict__ w2, const float* __restrict__ w3,
    const float* __restrict__ fc1w)
{
    int tid = blockIdx.x*256 + threadIdx.x;
    if (tid < 8192) { int c = tid >> 7, o = tid & 127; g_w2T[tid] = w2[o*64 + c]; }
    int t2 = tid - 8192;
    if (t2 >= 0 && t2 < 32768) { int c = t2 >> 8, o = t2 & 255; g_w3T[t2] = w3[o*128 + c]; }
    int t3 = tid - 40960;
    if (t3 >= 0 && t3 < 32768) { int n = t3 >> 7, o = t3 & 127; g_w1T[t3] = fc1w[o*256 + n]; }
}

// ---------------------------------------------------------------------------
// Kernel 1: kNN (one row/warp, redux argmax)
// ---------------------------------------------------------------------------
__global__ __launch_bounds__(256) void knn_kernel(const float* __restrict__ x) {
    __shared__ float xs0[NN], xs1[NN], xs2[NN], xxs[NN];
    int b      = blockIdx.x >> 5;
    int n_base = (blockIdx.x & 31) * 8;
    int tid = threadIdx.x;
    {
        float a0 = x[(b*NN + tid)*3 + 0];
        float a1 = x[(b*NN + tid)*3 + 1];
        float a2 = x[(b*NN + tid)*3 + 2];
        xs0[tid] = a0; xs1[tid] = a1; xs2[tid] = a2;
        xxs[tid] = a0*a0 + a1*a1 + a2*a2;
    }
    __syncthreads();
    int w = tid >> 5, lane = tid & 31;
    int i = n_base + w;

    float xi0 = xs0[i], xi1 = xs1[i], xi2 = xs2[i], xxi = xxs[i];
    unsigned m[8];
    #pragma unroll
    for (int t = 0; t < 8; t++) {
        int j = lane + 32*t;
        float dv = 2.f*(xi0*xs0[j] + xi1*xs1[j] + xi2*xs2[j]) - xxi - xxs[j];
        unsigned u = __float_as_uint(dv);
        m[t] = u ^ (unsigned)(((int)u >> 31) | 0x80000000);
    }

    int myj = 0;
    #pragma unroll 4
    for (int kk = 0; kk < KNB; kk++) {
        unsigned bv = m[0]; int bj = lane;
        #pragma unroll
        for (int t = 1; t < 8; t++)
            if (m[t] > bv) { bv = m[t]; bj = lane + 32*t; }
        unsigned vmax = __reduce_max_sync(0xffffffffu, bv);
        unsigned cand = (bv == vmax) ? (unsigned)bj : 0x7fffffffu;
        int jwin = (int)__reduce_min_sync(0xffffffffu, cand);
        if (lane == kk) myj = jwin;
        if ((jwin & 31) == lane) {
            int t = jwin >> 5;
            #pragma unroll
            for (int tt = 0; tt < 8; tt++) if (tt == t) m[tt] = 0u;
        }
    }
    if (lane < KNB) g_idx[(b*NN + i)*KNB + lane] = myj;
}

// ---------------------------------------------------------------------------
// Kernel 2a: mlp12  3 -> 64 -> 128
// ---------------------------------------------------------------------------
#define MLP12_SMEM ((96 + 2048 + 8192)*4)
__global__ __launch_bounds__(256) void mlp12_kernel(
    const float* __restrict__ x,
    const float* __restrict__ w1, const float* __restrict__ s1, const float* __restrict__ t1,
    const float* __restrict__ s2, const float* __restrict__ t2)
{
    extern __shared__ float sm[];
    float* xs   = sm;
    float* H1s  = sm + 96;
    float* W2Ts = sm + 2144;

    int tid = threadIdx.x;
    int row_base = blockIdx.x * 32;
    int b = row_base >> 8;
    int j0 = row_base & 255;

    if (tid < 96) xs[tid] = x[b*768 + j0*3 + tid];
    for (int e = tid; e < 2048; e += 256)
        ((float4*)W2Ts)[e] = ((const float4*)g_w2T)[e];
    __syncthreads();

    int w = tid >> 5, lane = tid & 31;
    int rb = w * 4;

    {
        int o2 = lane + 32;
        float a0 = w1[lane*3], a1 = w1[lane*3+1], a2 = w1[lane*3+2];
        float b0 = w1[o2*3],   b1 = w1[o2*3+1],   b2 = w1[o2*3+2];
        float sa = s1[lane], ta = t1[lane], sb = s1[o2], tb = t1[o2];
        #pragma unroll
        for (int i = 0; i < 4; i++) {
            int row = rb + i;
            float x0 = xs[row*3], x1 = xs[row*3+1], x2 = xs[row*3+2];
            H1s[row*64 + lane]      = fmaxf(sa*(a0*x0 + a1*x1 + a2*x2) + ta, 0.f);
            H1s[row*64 + lane + 32] = fmaxf(sb*(b0*x0 + b1*x1 + b2*x2) + tb, 0.f);
        }
    }
    __syncthreads();

    float acc[4][4];
    #pragma unroll
    for (int i = 0; i < 4; i++)
        #pragma unroll
        for (int k = 0; k < 4; k++) acc[i][k] = 0.f;
    #pragma unroll 8
    for (int c = 0; c < 64; c++) {
        float4 wv = *(const float4*)&W2Ts[c*128 + lane*4];
        #pragma unroll
        for (int i = 0; i < 4; i++) {
            float h = H1s[(rb+i)*64 + c];
            acc[i][0] += h*wv.x; acc[i][1] += h*wv.y;
            acc[i][2] += h*wv.z; acc[i][3] += h*wv.w;
        }
    }
    float sv[4], tv[4];
    #pragma unroll
    for (int k = 0; k < 4; k++) { sv[k] = s2[lane*4+k]; tv[k] = t2[lane*4+k]; }
    #pragma unroll
    for (int i = 0; i < 4; i++) {
        float4 o;
        o.x = fmaxf(sv[0]*acc[i][0] + tv[0], 0.f);
        o.y = fmaxf(sv[1]*acc[i][1] + tv[1], 0.f);
        o.z = fmaxf(sv[2]*acc[i][2] + tv[2], 0.f);
        o.w = fmaxf(sv[3]*acc[i][3] + tv[3], 0.f);
        *(float4*)&g_H2[(row_base + rb + i)*128 + lane*4] = o;
    }
}

// ---------------------------------------------------------------------------
// Kernel 2b: mlp3  128 -> 256, retiled: lane owns o-chunk lane*4 (conflict-free
// LDS.128 weight reads), warp owns 8 rows (broadcast h reads).
// ---------------------------------------------------------------------------
#define MLP3_SMEM ((8192 + 16384)*4)
__global__ __launch_bounds__(256, 2) void mlp3_kernel(
    const float* __restrict__ s3, const float* __restrict__ t3)
{
    extern __shared__ float sm[];
    float* H2s  = sm;          // [64 rows][128 c]
    float* W3Ts = sm + 8192;   // [128 c][128 o_local]

    int bid = blockIdx.x;
    int row0 = (bid >> 1) * 64;
    int oh = bid & 1;
    int tid = threadIdx.x;

    for (int e = tid; e < 2048; e += 256)
        ((float4*)H2s)[e] = ((const float4*)(g_H2 + row0*128))[e];
    for (int e = tid; e < 4096; e += 256) {
        int c = e >> 5, q = e & 31;
        ((float4*)W3Ts)[e] = *(const float4*)(g_w3T + c*256 + oh*128 + q*4);
    }
    __syncthreads();

    int w = tid >> 5, lane = tid & 31;
    int rb = w * 8;          // warp owns 8 rows
    int ob = lane * 4;       // lane owns 4 consecutive o (one 16B chunk)

    float acc[8][4];
    #pragma unroll
    for (int i = 0; i < 8; i++)
        #pragma unroll
        for (int k = 0; k < 4; k++) acc[i][k] = 0.f;

    #pragma unroll 2
    for (int c = 0; c < 128; c += 4) {
        // broadcast h for 8 rows (one float4 per row covers the 4 c's)
        float4 h[8];
        #pragma unroll
        for (int i = 0; i < 8; i++)
            h[i] = *(const float4*)&H2s[(rb+i)*128 + c];
        #pragma unroll
        for (int cc = 0; cc < 4; cc++) {
            float4 wv = *(const float4*)&W3Ts[(c+cc)*128 + ob];  // conflict-free
            #pragma unroll
            for (int i = 0; i < 8; i++) {
                float hv = ((const float*)&h[i])[cc];
                acc[i][0] += hv*wv.x; acc[i][1] += hv*wv.y;
                acc[i][2] += hv*wv.z; acc[i][3] += hv*wv.w;
            }
        }
    }
    float sv[4], tv[4];
    #pragma unroll
    for (int k = 0; k < 4; k++) { sv[k] = s3[oh*128 + ob + k]; tv[k] = t3[oh*128 + ob + k]; }
    #pragma unroll
    for (int i = 0; i < 8; i++) {
        int row = row0 + rb + i;
        float4 o;
        o.x = fmaxf(sv[0]*acc[i][0] + tv[0], 0.f);
        o.y = fmaxf(sv[1]*acc[i][1] + tv[1], 0.f);
        o.z = fmaxf(sv[2]*acc[i][2] + tv[2], 0.f);
        o.w = fmaxf(sv[3]*acc[i][3] + tv[3], 0.f);
        *(float4*)&g_H[row*256 + oh*128 + ob] = o;
    }
}

// ---------------------------------------------------------------------------
// Kernel 3: FUSED gather-max + fc1 + fc2 (round-6 exact)
// ---------------------------------------------------------------------------
#define MAXFC_SMEM ((16384 + 32768 + 5120)*4)
__global__ __launch_bounds__(512) void maxfc_kernel(
    const float* __restrict__ fc1_b,
    const float* __restrict__ fc2_w, const float* __restrict__ fc2_b,
    float* __restrict__ out)
{
    extern __shared__ float sm[];
    float* Ms   = sm;           // [n 256][c 64]
    float* Hs   = sm + 16384;   // [j 256][c 64]  (phase A)
    float* W1Ts = sm + 16384;   // [n 256][o 128] (phase B overlay)
    float* W2s  = sm + 49152;   // [q 40][o 128]
    int b = blockIdx.x >> 2, ct = blockIdx.x & 3;
    int tid = threadIdx.x;
    int w = tid >> 5, lane = tid & 31;

    // ---- Phase A: stage H channel-slice, gather-max into Ms
    for (int e = tid; e < 4096; e += 512) {
        int j = e >> 4, q = e & 15;
        ((float4*)Hs)[e] = *(const float4*)(g_H + (b*256 + j)*256 + ct*64 + q*4);
    }
    __syncthreads();

    #pragma unroll 2
    for (int t = 0; t < 16; t += 2) {
        int n0 = w*16 + t, n1 = n0 + 1;
        const int4* ip0 = (const int4*)(g_idx + (b*NN + n0)*KNB);
        const int4* ip1 = (const int4*)(g_idx + (b*NN + n1)*KNB);
        float a0 = NEG_INF, a1 = NEG_INF, c0 = NEG_INF, c1 = NEG_INF;
        #pragma unroll
        for (int q = 0; q < 5; q++) {
            int4 u = ip0[q];
            int4 v = ip1[q];
            a0 = fmaxf(a0, Hs[u.x*64 + lane]); a1 = fmaxf(a1, Hs[u.x*64 + lane + 32]);
            c0 = fmaxf(c0, Hs[v.x*64 + lane]); c1 = fmaxf(c1, Hs[v.x*64 + lane + 32]);
            a0 = fmaxf(a0, Hs[u.y*64 + lane]); a1 = fmaxf(a1, Hs[u.y*64 + lane + 32]);
            c0 = fmaxf(c0, Hs[v.y*64 + lane]); c1 = fmaxf(c1, Hs[v.y*64 + lane + 32]);
            a0 = fmaxf(a0, Hs[u.z*64 + lane]); a1 = fmaxf(a1, Hs[u.z*64 + lane + 32]);
            c0 = fmaxf(c0, Hs[v.z*64 + lane]); c1 = fmaxf(c1, Hs[v.z*64 + lane + 32]);
            a0 = fmaxf(a0, Hs[u.w*64 + lane]); a1 = fmaxf(a1, Hs[u.w*64 + lane + 32]);
            c0 = fmaxf(c0, Hs[v.w*64 + lane]); c1 = fmaxf(c1, Hs[v.w*64 + lane + 32]);
        }
        Ms[n0*64 + lane] = a0; Ms[n0*64 + lane + 32] = a1;
        Ms[n1*64 + lane] = c0; Ms[n1*64 + lane + 32] = c1;
    }
    __syncthreads();

    // ---- Phase B: load weights over dead Hs region, then fc1 + fc2
    for (int e = tid; e < 8192; e += 512)
        ((float4*)W1Ts)[e] = ((const float4*)g_w1T)[e];
    for (int e = tid; e < 1280; e += 512)
        ((float4*)W2s)[e] = ((const float4*)fc2_w)[e];
    __syncthreads();

    int half = w >> 3, w8 = w & 7;
    int o_base = w8*16 + (lane >> 4)*8;
    int c_base = (lane & 15)*4;

    float acc[4][8];
    #pragma unroll
    for (int i = 0; i < 4; i++)
        #pragma unroll
        for (int k = 0; k < 8; k++) acc[i][k] = 0.f;

    int n0 = half*128;
    #pragma unroll 4
    for (int n = n0; n < n0 + 128; n++) {
        float4 mv = *(const float4*)&Ms[n*64 + c_base];
        float4 wa = *(const float4*)&W1Ts[n*128 + o_base];
        float4 wb = *(const float4*)&W1Ts[n*128 + o_base + 4];
        float mm[4] = {mv.x, mv.y, mv.z, mv.w};
        float ww[8] = {wa.x, wa.y, wa.z, wa.w, wb.x, wb.y, wb.z, wb.w};
        #pragma unroll
        for (int i = 0; i < 4; i++)
            #pragma unroll
            for (int k = 0; k < 8; k++)
                acc[i][k] += mm[i]*ww[k];
    }
    __syncthreads();

    float* Rs = sm;
    float* Gs = sm + 8320;
    if (half == 1) {
        #pragma unroll
        for (int i = 0; i < 4; i++)
            #pragma unroll
            for (int k = 0; k < 8; k++)
                Rs[(c_base + i)*129 + o_base + k] = acc[i][k];
    }
    __syncthreads();
    if (half == 0) {
        float b1v[8];
        #pragma unroll
        for (int k = 0; k < 8; k++) b1v[k] = fc1_b[o_base + k];
        #pragma unroll
        for (int i = 0; i < 4; i++)
            #pragma unroll
            for (int k = 0; k < 8; k++)
                Gs[(c_base + i)*129 + o_base + k] =
                    fmaxf(acc[i][k] + Rs[(c_base + i)*129 + o_base + k] + b1v[k], 0.f);
    }
    __syncthreads();

    if (w < 8) {
        float acc2[2][5];
        #pragma unroll
        for (int h = 0; h < 2; h++)
            #pragma unroll
            for (int q = 0; q < 5; q++) acc2[h][q] = 0.f;
        #pragma unroll 4
        for (int o = 0; o < 128; o++) {
            float ga = Gs[lane*129 + o];
            float gb = Gs[(lane + 32)*129 + o];
            #pragma unroll
            for (int q = 0; q < 5; q++) {
                float wv = W2s[(w*5 + q)*128 + o];
                acc2[0][q] += ga*wv;
                acc2[1][q] += gb*wv;
            }
        }
        #pragma unroll
        for (int h = 0; h < 2; h++) {
            int cg = ct*64 + lane + h*32;
            #pragma unroll
            for (int q = 0; q < 5; q++)
                out[(b*256 + cg)*40 + w*5 + q] = acc2[h][q] + fc2_b[w*5 + q];
        }
    }
}

extern "C" void kernel_launch(void* const* d_in, const int* in_sizes, int n_in,
                              void* d_out, int out_size) {
    const float* x    = (const float*)d_in[0];
    const float* w1   = (const float*)d_in[1];
    const float* s1   = (const float*)d_in[2];
    const float* t1   = (const float*)d_in[3];
    const float* w2   = (const float*)d_in[4];
    const float* s2   = (const float*)d_in[5];
    const float* t2   = (const float*)d_in[6];
    const float* w3   = (const float*)d_in[7];
    const float* s3   = (const float*)d_in[8];
    const float* t3   = (const float*)d_in[9];
    const float* fc1w = (const float*)d_in[10];
    const float* fc1b = (const float*)d_in[11];
    const float* fc2w = (const float*)d_in[12];
    const float* fc2b = (const float*)d_in[13];
    float* out = (float*)d_out;

    cudaFuncSetAttribute(mlp12_kernel, cudaFuncAttributeMaxDynamicSharedMemorySize, MLP12_SMEM);
    cudaFuncSetAttribute(mlp3_kernel,  cudaFuncAttributeMaxDynamicSharedMemorySize, MLP3_SMEM);
    cudaFuncSetAttribute(maxfc_kernel, cudaFuncAttributeMaxDynamicSharedMemorySize, MAXFC_SMEM);

    transpose_kernel<<<288, 256>>>(w2, w3, fc1w);
    knn_kernel<<<1024, 256>>>(x);
    mlp12_kernel<<<256, 256, MLP12_SMEM>>>(x, w1, s1, t1, s2, t2);
    mlp3_kernel<<<256, 256, MLP3_SMEM>>>(s3, t3);
    maxfc_kernel<<<128, 512, MAXFC_SMEM>>>(fc1b, fc2w, fc2b, out);
}